// round 9
// baseline (speedup 1.0000x reference)
#include <cuda_runtime.h>
#include <cuda_bf16.h>
#include <cstdint>

#define CIN 128
#define C 64
#define H2f 0.01f
#define NNODES 50000
#define NEDGES 800000
#define TE 128
#define GSB 72          // smem tile row stride in bf16 (144B)

#define GT_BYTES (TE * GSB * 2)
#define SMEM_EDGE (2 * GT_BYTES + GT_BYTES + 4 * TE * 12)

__device__ float g_deg[NNODES];
__device__ float g_W[NEDGES];
__device__ float g_buf[3][(long)NNODES * C];
__device__ uint32_t g_xbf[(long)NNODES * C / 2];   // bf16 mirror of x_cur

// ---------------- helpers ----------------
__device__ __forceinline__ uint32_t smem_u32(const void* p) {
    uint32_t a;
    asm("{ .reg .u64 t; cvta.to.shared.u64 t, %1; cvt.u32.u64 %0, t; }"
        : "=r"(a) : "l"(p));
    return a;
}
__device__ __forceinline__ float tanh_fast(float x) {
    float y;
    asm("tanh.approx.f32 %0, %1;" : "=f"(y) : "f"(x));
    return y;
}
// pack bf16x2: lo = a, hi = b
__device__ __forceinline__ uint32_t bf16x2_pack(float a, float b) {
    uint32_t r;
    asm("cvt.rn.satfinite.bf16x2.f32 %0, %1, %2;" : "=r"(r) : "f"(b), "f"(a));
    return r;
}
// g = w2 * (xi - xj), all bf16x2 packed in u32
__device__ __forceinline__ uint32_t gdiff(uint32_t xi, uint32_t xj, uint32_t w2) {
    __nv_bfloat162 a = *(__nv_bfloat162*)&xi;
    __nv_bfloat162 b = *(__nv_bfloat162*)&xj;
    __nv_bfloat162 w = *(__nv_bfloat162*)&w2;
    __nv_bfloat162 r = __hmul2(w, __hsub2(a, b));
    return *(uint32_t*)&r;
}
__device__ __forceinline__ void ldsm4(uint32_t (&r)[4], uint32_t addr) {
    asm volatile("ldmatrix.sync.aligned.m8n8.x4.shared.b16 {%0,%1,%2,%3}, [%4];"
        : "=r"(r[0]), "=r"(r[1]), "=r"(r[2]), "=r"(r[3]) : "r"(addr));
}
__device__ __forceinline__ void mma_bf16(float (&d)[4], const uint32_t (&a)[4],
                                         const uint32_t* b) {
    asm volatile("mma.sync.aligned.m16n8k16.row.col.f32.bf16.bf16.f32 "
        "{%0,%1,%2,%3}, {%4,%5,%6,%7}, {%8,%9}, {%0,%1,%2,%3};"
        : "+f"(d[0]), "+f"(d[1]), "+f"(d[2]), "+f"(d[3])
        : "r"(a[0]), "r"(a[1]), "r"(a[2]), "r"(a[3]), "r"(b[0]), "r"(b[1]));
}

// ---------------- setup kernels ----------------
__global__ void __launch_bounds__(256) k_pz(const float* __restrict__ xn,
                                            const float* __restrict__ K1,
                                            int nN, int nPB) {
    if (blockIdx.x >= nPB) {
        int i = (blockIdx.x - nPB) * 256 + threadIdx.x;
        if (i < nN) g_deg[i] = 0.0f;
        return;
    }
    __shared__ float Ks[C * CIN];
    __shared__ float xs[CIN * 64];
    int tid = threadIdx.x;
    for (int i = tid; i < C * CIN; i += 256) Ks[i] = K1[i];
    int n0 = blockIdx.x * 64;
    for (int i = tid; i < CIN * 64; i += 256) {
        int k = i >> 6, nl = i & 63;
        int n = n0 + nl;
        xs[i] = (n < nN) ? xn[(long)k * nN + n] : 0.0f;
    }
    __syncthreads();
    int nl = tid & 63;
    int cb = (tid >> 6) * 16;
    float acc[16];
#pragma unroll
    for (int j = 0; j < 16; j++) acc[j] = 0.0f;
    for (int k = 0; k < CIN; k++) {
        float xv = xs[k * 64 + nl];
#pragma unroll
        for (int j = 0; j < 16; j++) acc[j] = fmaf(Ks[(cb + j) * CIN + k], xv, acc[j]);
    }
    int n = n0 + nl;
    if (n < nN) {
#pragma unroll
        for (int j = 0; j < 16; j++) {
            float v = fmaxf(acc[j], 0.0f);
            g_buf[0][(long)n * C + cb + j] = v;
            g_buf[1][(long)n * C + cb + j] = v;
            g_buf[2][(long)n * C + cb + j] = v;
        }
#pragma unroll
        for (int j = 0; j < 8; j++) {
            float a = fmaxf(acc[2 * j], 0.0f), b = fmaxf(acc[2 * j + 1], 0.0f);
            g_xbf[(long)n * 32 + cb / 2 + j] = bf16x2_pack(a, b);
        }
    }
}

__global__ void k_degree(const int* __restrict__ Jv, int nE) {
    int e = blockIdx.x * blockDim.x + threadIdx.x;
    if (e < nE) atomicAdd(&g_deg[Jv[e]], 1.0f);
}

__global__ void k_Wd(const int* __restrict__ Iv, const int* __restrict__ Jv, int nE) {
    int e = blockIdx.x * blockDim.x + threadIdx.x;
    if (e < nE)
        g_W[e] = rsqrtf(g_deg[Iv[e]] + 1.0f) * rsqrtf(g_deg[Jv[e]] + 1.0f);
}

// A = 2*x_cur - x_old; also refresh bf16 mirror of x_cur
__global__ void k_init(int curI, int oldI, int nxtI, int n4) {
    int i = blockIdx.x * blockDim.x + threadIdx.x;
    if (i >= n4) return;
    float4 a = ((const float4*)g_buf[curI])[i];
    float4 b = ((const float4*)g_buf[oldI])[i];
    ((float4*)g_buf[nxtI])[i] = make_float4(2.0f * a.x - b.x, 2.0f * a.y - b.y,
                                            2.0f * a.z - b.z, 2.0f * a.w - b.w);
    ((uint2*)g_xbf)[i] = make_uint2(bf16x2_pack(a.x, a.y), bf16x2_pack(a.z, a.w));
}

// ---------------- hot kernel: mma.sync bf16, software-pipelined ----------------
// PhaseA = idx-prefetch(k+2) + GEMM1(k) interleaved with bf16 x-gather(k+1)
// + tanh->Tt ; sync ; PhaseB = GEMM2(k) + RED scatter(k).
__global__ void __launch_bounds__(256, 2)
k_edge(int aI, const int* __restrict__ Iv, const int* __restrict__ Jv,
       const float* __restrict__ Km, int nE)
{
    extern __shared__ __align__(16) char smem[];
    __nv_bfloat16* GtA = (__nv_bfloat16*)smem;
    __nv_bfloat16* GtB = (__nv_bfloat16*)(smem + GT_BYTES);
    __nv_bfloat16* Tt  = (__nv_bfloat16*)(smem + 2 * GT_BYTES);
    int*   sI = (int*)(smem + 3 * GT_BYTES);          // [4][TE]
    int*   sJ = sI + 4 * TE;
    float* sW = (float*)(sJ + 4 * TE);

    int tid = threadIdx.x, lane = tid & 31, wid = tid >> 5;
    int gid = lane >> 2, tig = lane & 3;
    int wm = wid & 3, wn = wid >> 2;
    int mbase = wm * 32, nbase = wn * 32;

    // ---- persistent B fragments ----
    uint32_t bfr[4][4][2];
    {
        int n = nbase + gid;
#pragma unroll
        for (int nt = 0; nt < 4; nt++) {
            const float* kr = Km + (long)(n + nt * 8) * 64;
#pragma unroll
            for (int kt = 0; kt < 4; kt++) {
                int k0 = kt * 16 + tig * 2;
                bfr[kt][nt][0] = bf16x2_pack(kr[k0], kr[k0 + 1]);
                bfr[kt][nt][1] = bf16x2_pack(kr[k0 + 8], kr[k0 + 9]);
            }
        }
    }

    uint32_t gba = smem_u32(GtA), gbb = smem_u32(GtB), tb = smem_u32(Tt);
    int lrow = (lane & 7) + ((lane >> 3) & 1) * 8;
    int lcol = ((lane >> 4) & 1) * 8;

    const uint32_t* xb = g_xbf;        // bf16x2 per (node, ch-pair); 32 u32/node
    float* A = g_buf[aI];
    long stride = (long)gridDim.x * TE;
    long e0 = (long)blockIdx.x * TE;

    auto load_idx = [&](long eb, int s) {
        if (tid < TE) {
            long e = eb + tid;
            bool ok = e < (long)nE;
            sI[s * TE + tid] = ok ? Iv[e] : 0;
            sJ[s * TE + tid] = ok ? Jv[e] : 0;
            sW[s * TE + tid] = ok ? g_W[e] : 0.0f;
        }
    };

    // ---- prologue: idx slots 0,1; gather tile 0 into GtA ----
    load_idx(e0, 0);
    load_idx(e0 + stride, 1);
    __syncthreads();
    {
        int eb = wid * 16;
#pragma unroll 4
        for (int el = 0; el < 16; el++) {
            int e = eb + el;
            uint32_t w2 = bf16x2_pack(sW[e], sW[e]);
            uint32_t xi = xb[(long)sI[e] * 32 + lane];
            uint32_t xj = xb[(long)sJ[e] * 32 + lane];
            *(uint32_t*)((char*)GtA + e * (GSB * 2) + lane * 4) = gdiff(xi, xj, w2);
        }
    }

    int s0 = 0;
    int curbuf = 0;
    for (; e0 < nE; e0 += stride) {
        int s1 = (s0 + 1) & 3, s2 = (s0 + 2) & 3;
        uint32_t gcur = curbuf ? gbb : gba;
        char* gnext = (char*)(curbuf ? GtA : GtB);
        __syncthreads();
        // ---- Phase A ----
        load_idx(e0 + 2 * stride, s2);

        float acc[2][4][4];
#pragma unroll
        for (int mt = 0; mt < 2; mt++)
#pragma unroll
            for (int nt = 0; nt < 4; nt++)
#pragma unroll
                for (int q = 0; q < 4; q++) acc[mt][nt][q] = 0.0f;

        const int* sIc = sI + s1 * TE;
        const int* sJc = sJ + s1 * TE;
        const float* sWc = sW + s1 * TE;
        int ebg = wid * 16;
        uint32_t xiu[8], xju[8];
        // wave 0 loads (edges 0-7, tile k+1)
#pragma unroll
        for (int el = 0; el < 8; el++) {
            int e = ebg + el;
            xiu[el] = xb[(long)sIc[e] * 32 + lane];
            xju[el] = xb[(long)sJc[e] * 32 + lane];
        }
        // GEMM1 kt = 0,1
#pragma unroll
        for (int kt = 0; kt < 2; kt++)
#pragma unroll
            for (int mt = 0; mt < 2; mt++) {
                uint32_t af[4];
                ldsm4(af, gcur + (mbase + mt * 16 + lrow) * (GSB * 2)
                              + (kt * 16 + lcol) * 2);
#pragma unroll
                for (int nt = 0; nt < 4; nt++) mma_bf16(acc[mt][nt], af, bfr[kt][nt]);
            }
        // store wave 0
#pragma unroll
        for (int el = 0; el < 8; el++) {
            int e = ebg + el;
            uint32_t w2 = bf16x2_pack(sWc[e], sWc[e]);
            *(uint32_t*)(gnext + e * (GSB * 2) + lane * 4) = gdiff(xiu[el], xju[el], w2);
        }
        // wave 1 loads (edges 8-15)
#pragma unroll
        for (int el = 0; el < 8; el++) {
            int e = ebg + 8 + el;
            xiu[el] = xb[(long)sIc[e] * 32 + lane];
            xju[el] = xb[(long)sJc[e] * 32 + lane];
        }
        // GEMM1 kt = 2,3
#pragma unroll
        for (int kt = 2; kt < 4; kt++)
#pragma unroll
            for (int mt = 0; mt < 2; mt++) {
                uint32_t af[4];
                ldsm4(af, gcur + (mbase + mt * 16 + lrow) * (GSB * 2)
                              + (kt * 16 + lcol) * 2);
#pragma unroll
                for (int nt = 0; nt < 4; nt++) mma_bf16(acc[mt][nt], af, bfr[kt][nt]);
            }
        // store wave 1
#pragma unroll
        for (int el = 0; el < 8; el++) {
            int e = ebg + 8 + el;
            uint32_t w2 = bf16x2_pack(sWc[e], sWc[e]);
            *(uint32_t*)(gnext + e * (GSB * 2) + lane * 4) = gdiff(xiu[el], xju[el], w2);
        }
        // tanh -> Tt
#pragma unroll
        for (int mt = 0; mt < 2; mt++) {
            int er = mbase + mt * 16 + gid;
#pragma unroll
            for (int nt = 0; nt < 4; nt++) {
                int o = nbase + nt * 8 + tig * 2;
                *(uint32_t*)((char*)Tt + er * (GSB * 2) + o * 2) =
                    bf16x2_pack(tanh_fast(acc[mt][nt][0]), tanh_fast(acc[mt][nt][1]));
                *(uint32_t*)((char*)Tt + (er + 8) * (GSB * 2) + o * 2) =
                    bf16x2_pack(tanh_fast(acc[mt][nt][2]), tanh_fast(acc[mt][nt][3]));
            }
        }
        __syncthreads();
        // ---- Phase B: GEMM2 + scatter ----
#pragma unroll
        for (int mt = 0; mt < 2; mt++)
#pragma unroll
            for (int nt = 0; nt < 4; nt++)
#pragma unroll
                for (int q = 0; q < 4; q++) acc[mt][nt][q] = 0.0f;
#pragma unroll
        for (int kt = 0; kt < 4; kt++)
#pragma unroll
            for (int mt = 0; mt < 2; mt++) {
                uint32_t af[4];
                ldsm4(af, tb + (mbase + mt * 16 + lrow) * (GSB * 2)
                             + (kt * 16 + lcol) * 2);
#pragma unroll
                for (int nt = 0; nt < 4; nt++) mma_bf16(acc[mt][nt], af, bfr[kt][nt]);
            }
        const int* sIs = sI + s0 * TE;
        const int* sJs = sJ + s0 * TE;
        const float* sWs = sW + s0 * TE;
#pragma unroll
        for (int mt = 0; mt < 2; mt++) {
#pragma unroll
            for (int half = 0; half < 2; half++) {
                int er = mbase + mt * 16 + gid + half * 8;
                float s = H2f * sWs[er];
                long ni = sIs[er], nj = sJs[er];
                float* pi = A + ni * 64;
                float* pj = A + nj * 64;
#pragma unroll
                for (int nt = 0; nt < 4; nt++) {
                    int c = nbase + nt * 8 + tig * 2;
                    float v0 = s * acc[mt][nt][2 * half];
                    float v1 = s * acc[mt][nt][2 * half + 1];
                    asm volatile("red.global.add.v2.f32 [%0], {%1, %2};"
                                 :: "l"(pi + c), "f"(-v0), "f"(-v1) : "memory");
                    asm volatile("red.global.add.v2.f32 [%0], {%1, %2};"
                                 :: "l"(pj + c), "f"(v0), "f"(v1) : "memory");
                }
            }
        }
        s0 = s1;
        curbuf ^= 1;
    }
}

// out[n][o] = sum_c KNclose[o][c] * x[n][c]
__global__ void __launch_bounds__(128) k_out(int xIdx, const float* __restrict__ KNc,
                                             float* __restrict__ out, int nN, int nOut) {
    __shared__ float Ks[40 * C];
    for (int i = threadIdx.x; i < nOut * C; i += 128) Ks[i] = KNc[i];
    __syncthreads();
    int n = blockIdx.x * 128 + threadIdx.x;
    if (n >= nN) return;
    const float* xr = g_buf[xIdx] + (long)n * C;
    float xv[C];
#pragma unroll
    for (int q = 0; q < C / 4; q++) {
        float4 v = ((const float4*)xr)[q];
        xv[4 * q] = v.x; xv[4 * q + 1] = v.y; xv[4 * q + 2] = v.z; xv[4 * q + 3] = v.w;
    }
    for (int o = 0; o < nOut; o++) {
        float acc = 0.0f;
#pragma unroll
        for (int c = 0; c < C; c++) acc = fmaf(Ks[o * C + c], xv[c], acc);
        out[(long)n * nOut + o] = acc;
    }
}

extern "C" void kernel_launch(void* const* d_in, const int* in_sizes, int n_in,
                              void* d_out, int out_size) {
    const float* xn = (const float*)d_in[0];
    const int* Iv = (const int*)d_in[1];
    const int* Jv = (const int*)d_in[2];
    int idx = 3;
    if (n_in >= 7 && in_sizes[3] == 1) idx = 4;   // skip scalar n_nodes input
    const float* K1  = (const float*)d_in[idx];
    const float* KN2 = (const float*)d_in[idx + 1];
    const float* KNc = (const float*)d_in[idx + 2];
    int nE = in_sizes[1];
    int nN = in_sizes[0] / CIN;
    int nLayer = in_sizes[idx + 1] / (C * C);
    int nOut = in_sizes[idx + 2] / C;
    float* out = (float*)d_out;

    cudaFuncSetAttribute(k_edge, cudaFuncAttributeMaxDynamicSharedMemorySize,
                         SMEM_EDGE);

    int nPB = (nN + 63) / 64;
    int nZB = (nN + 255) / 256;
    k_pz<<<nPB + nZB, 256>>>(xn, K1, nN, nPB);            // launch 0
    k_degree<<<(nE + 255) / 256, 256>>>(Jv, nE);          // launch 1
    k_Wd<<<(nE + 255) / 256, 256>>>(Iv, Jv, nE);          // launch 2

    int cur = 0, old = 1, nxt = 2;
    int n4 = nN * C / 4;
    for (int l = 0; l < nLayer; l++) {
        if (l > 0)
            k_init<<<(n4 + 255) / 256, 256>>>(cur, old, nxt, n4);
        k_edge<<<304, 256, SMEM_EDGE>>>(nxt, Iv, Jv, KN2 + (long)l * C * C, nE);
        int t = old; old = cur; cur = nxt; nxt = t;
    }
    k_out<<<(nN + 127) / 128, 128>>>(cur, KNc, out, nN, nOut);
}